// round 10
// baseline (speedup 1.0000x reference)
#include <cuda_runtime.h>
#include <cuda_bf16.h>
#include <cstdint>

#define H        128
#define NE       400000
#define NN       50000
#define THREADS  256
#define MTILE    64
#define SA2      68    // uint2 stride for A kpairs (mod 16 == 4 -> conflict-free)

// scatter-add accumulator; zero-initialized at module load, re-zeroed by
// node_kernel after consumption -> invariant: zero at start of every launch.
__device__ float g_agg[NN * H];
// prepacked split-bf16 weights: 11 chunks x [64 kpairs][128 cols] uint2(hi,lo)
__device__ uint2 g_wB[11 * 8192];

// ---------------------------------------------------------------- helpers
__device__ __forceinline__ void split2(float2 v, uint32_t& hi, uint32_t& lo) {
    __nv_bfloat162 h = __float22bfloat162_rn(v);
    float2 hf = __bfloat1622float2(h);
    __nv_bfloat162 l = __float22bfloat162_rn(make_float2(v.x - hf.x, v.y - hf.y));
    hi = *(uint32_t*)&h;
    lo = *(uint32_t*)&l;
}
__device__ __forceinline__ uint2 splitp(float2 v) {
    uint2 r; split2(v, r.x, r.y); return r;
}

__device__ __forceinline__ void mma_bf16(float d[4], const uint32_t a[4],
                                         uint32_t b0, uint32_t b1) {
    asm volatile(
        "mma.sync.aligned.m16n8k16.row.col.f32.bf16.bf16.f32 "
        "{%0,%1,%2,%3}, {%4,%5,%6,%7}, {%8,%9}, {%0,%1,%2,%3};"
        : "+f"(d[0]), "+f"(d[1]), "+f"(d[2]), "+f"(d[3])
        : "r"(a[0]), "r"(a[1]), "r"(a[2]), "r"(a[3]), "r"(b0), "r"(b1));
}

// ---------------------------------------------------------------- wprep
// Pack all weight chunks once: g_wB[chunk*8192 + kp*128 + col] = split(W[2kp..2kp+1][col])
// chunks: 0-2 eW1(k0=0,128,256), 3 eW2, 4 eW3, 5 eW4, 6-7 nW1(k0=0,128), 8 nW2, 9 nW3, 10 nW4
__global__ void wprep_kernel(const float* __restrict__ eW1, const float* __restrict__ eW2,
                             const float* __restrict__ eW3, const float* __restrict__ eW4,
                             const float* __restrict__ nW1, const float* __restrict__ nW2,
                             const float* __restrict__ nW3, const float* __restrict__ nW4)
{
    int i = blockIdx.x * blockDim.x + threadIdx.x;
    if (i >= 11 * 8192) return;
    int chunk = i >> 13, e = i & 8191;
    int kp = e >> 7, col = e & 127;
    const float* W; int k0;
    switch (chunk) {
        case 0:  W = eW1; k0 = 0;   break;
        case 1:  W = eW1; k0 = 128; break;
        case 2:  W = eW1; k0 = 256; break;
        case 3:  W = eW2; k0 = 0;   break;
        case 4:  W = eW3; k0 = 0;   break;
        case 5:  W = eW4; k0 = 0;   break;
        case 6:  W = nW1; k0 = 0;   break;
        case 7:  W = nW1; k0 = 128; break;
        case 8:  W = nW2; k0 = 0;   break;
        case 9:  W = nW3; k0 = 0;   break;
        default: W = nW4; k0 = 0;   break;
    }
    float2 v = make_float2(W[(size_t)(k0 + 2 * kp)     * H + col],
                           W[(size_t)(k0 + 2 * kp + 1) * H + col]);
    g_wB[i] = splitp(v);
}

// ---------------------------------------------------------------- gemm
// Warp tile m32 x n32: rows rb..rb+31, scalar cols nb0..nb0+31.
// A from smem (split uint2 per kpair); B fragments straight from global
// prepacked g_wB chunk (L1/L2-hot: one 64KB chunk shared by all CTAs).
__device__ __forceinline__ void gemm64(const uint2* sA, const uint2* __restrict__ gB,
                                       float acc[2][4][4], int rb, int nb0) {
    int lane = threadIdx.x & 31;
    int gid  = lane >> 2, tig = lane & 3;
    const uint2* A0 = sA + (rb + gid) * SA2;
    #pragma unroll 1
    for (int ks = 0; ks < 8; ++ks) {
        int kp = ks * 8 + tig;
        uint32_t ah[2][4], al[2][4];
        #pragma unroll
        for (int mb = 0; mb < 2; ++mb) {
            const uint2* Ar0 = A0 + mb * 16 * SA2 + kp;
            const uint2* Ar8 = Ar0 + 8 * SA2;
            uint2 q0 = Ar0[0], q1 = Ar8[0], q2 = Ar0[4], q3 = Ar8[4];
            ah[mb][0] = q0.x; al[mb][0] = q0.y;
            ah[mb][1] = q1.x; al[mb][1] = q1.y;
            ah[mb][2] = q2.x; al[mb][2] = q2.y;
            ah[mb][3] = q3.x; al[mb][3] = q3.y;
        }
        const uint2* Bp0 = gB + kp * 128 + nb0 + gid;
        const uint2* Bp1 = Bp0 + 4 * 128;
        #pragma unroll
        for (int nt = 0; nt < 4; ++nt) {
            uint2 b0 = __ldg(Bp0 + nt * 8), b1 = __ldg(Bp1 + nt * 8);
            #pragma unroll
            for (int mb = 0; mb < 2; ++mb) {
                mma_bf16(acc[mb][nt], ah[mb], b0.x, b1.x);
                mma_bf16(acc[mb][nt], al[mb], b0.x, b1.x);
                mma_bf16(acc[mb][nt], ah[mb], b0.y, b1.y);
            }
        }
    }
}

__device__ __forceinline__ void zero_acc(float acc[2][4][4]) {
    #pragma unroll
    for (int mb = 0; mb < 2; ++mb)
        #pragma unroll
        for (int nt = 0; nt < 4; ++nt)
            #pragma unroll
            for (int c = 0; c < 4; ++c) acc[mb][nt][c] = 0.0f;
}

// bias + ReLU + LayerNorm (rows split across 4 n-warps); split-store into sA
__device__ __forceinline__ void epi_ln(float acc[2][4][4], const float* sPar, int l,
                                       uint2* sA, float2 (*sPart)[4], int rb, int nb0,
                                       int wn) {
    int lane = threadIdx.x & 31;
    int gid  = lane >> 2, tig = lane & 3;
    const float* bb = sPar + l * 3 * 128;
    const float* gg = bb + 128;
    const float* tt = bb + 256;
    float s[4] = {0.f, 0.f, 0.f, 0.f}, s2[4] = {0.f, 0.f, 0.f, 0.f};
    #pragma unroll
    for (int mb = 0; mb < 2; ++mb)
        #pragma unroll
        for (int nt = 0; nt < 4; ++nt) {
            int col = nb0 + nt * 8 + 2 * tig;
            float2 b = *(const float2*)(bb + col);
            float t0 = fmaxf(acc[mb][nt][0] + b.x, 0.f);
            float t1 = fmaxf(acc[mb][nt][1] + b.y, 0.f);
            float t2 = fmaxf(acc[mb][nt][2] + b.x, 0.f);
            float t3 = fmaxf(acc[mb][nt][3] + b.y, 0.f);
            acc[mb][nt][0] = t0; acc[mb][nt][1] = t1;
            acc[mb][nt][2] = t2; acc[mb][nt][3] = t3;
            s[2*mb]   += t0 + t1; s2[2*mb]   = fmaf(t0, t0, fmaf(t1, t1, s2[2*mb]));
            s[2*mb+1] += t2 + t3; s2[2*mb+1] = fmaf(t2, t2, fmaf(t3, t3, s2[2*mb+1]));
        }
    #pragma unroll
    for (int m = 1; m <= 2; m <<= 1)
        #pragma unroll
        for (int k = 0; k < 4; ++k) {
            s[k]  += __shfl_xor_sync(0xffffffffu, s[k],  m);
            s2[k] += __shfl_xor_sync(0xffffffffu, s2[k], m);
        }
    int R[4] = {rb + gid, rb + gid + 8, rb + 16 + gid, rb + 24 + gid};
    if (tig == 0) {
        #pragma unroll
        for (int k = 0; k < 4; ++k) sPart[R[k]][wn] = make_float2(s[k], s2[k]);
    }
    __syncthreads();
    float mean[4], inv[4];
    #pragma unroll
    for (int k = 0; k < 4; ++k) {
        float2 p0 = sPart[R[k]][0], p1 = sPart[R[k]][1];
        float2 p2 = sPart[R[k]][2], p3 = sPart[R[k]][3];
        float sm = (p0.x + p1.x) + (p2.x + p3.x);
        float sq = (p0.y + p1.y) + (p2.y + p3.y);
        mean[k] = sm * 0.0078125f;
        inv[k]  = rsqrtf(fmaf(-mean[k], mean[k], sq * 0.0078125f) + 1e-5f);
    }
    #pragma unroll
    for (int mb = 0; mb < 2; ++mb)
        #pragma unroll
        for (int nt = 0; nt < 4; ++nt) {
            int col = nb0 + nt * 8 + 2 * tig;
            int kpo = col >> 1;
            float2 g = *(const float2*)(gg + col);
            float2 t = *(const float2*)(tt + col);
            float2 va, vb;
            va.x = fmaf((acc[mb][nt][0] - mean[2*mb]) * inv[2*mb], g.x, t.x);
            va.y = fmaf((acc[mb][nt][1] - mean[2*mb]) * inv[2*mb], g.y, t.y);
            vb.x = fmaf((acc[mb][nt][2] - mean[2*mb+1]) * inv[2*mb+1], g.x, t.x);
            vb.y = fmaf((acc[mb][nt][3] - mean[2*mb+1]) * inv[2*mb+1], g.y, t.y);
            sA[R[2*mb]   * SA2 + kpo] = splitp(va);
            sA[R[2*mb+1] * SA2 + kpo] = splitp(vb);
        }
}

// final layer: acc + b4 -> f32 staging (stride 132 floats; ALIASES sA)
__device__ __forceinline__ void epi_final(float acc[2][4][4], const float* sPar,
                                          float* sC, int rb, int nb0) {
    int lane = threadIdx.x & 31;
    int gid  = lane >> 2, tig = lane & 3;
    const float* b4 = sPar + 9 * 128;
    #pragma unroll
    for (int mb = 0; mb < 2; ++mb) {
        int r0 = rb + mb * 16 + gid;
        #pragma unroll
        for (int nt = 0; nt < 4; ++nt) {
            int col = nb0 + nt * 8 + 2 * tig;
            float2 b = *(const float2*)(b4 + col);
            float2 va, vb;
            va.x = acc[mb][nt][0] + b.x; va.y = acc[mb][nt][1] + b.y;
            vb.x = acc[mb][nt][2] + b.x; vb.y = acc[mb][nt][3] + b.y;
            *(float2*)(sC + r0 * 132 + col)       = va;
            *(float2*)(sC + (r0 + 8) * 132 + col) = vb;
        }
    }
}

// ---------------------------------------------------------------- edge kernel
__global__ void __launch_bounds__(THREADS, 2)
edge_kernel(const float* __restrict__ x, const float* __restrict__ edge_attr,
            const int* __restrict__ edge_index,
            const float* __restrict__ b1, const float* __restrict__ g1, const float* __restrict__ t1,
            const float* __restrict__ b2, const float* __restrict__ g2, const float* __restrict__ t2,
            const float* __restrict__ b3, const float* __restrict__ g3, const float* __restrict__ t3,
            const float* __restrict__ b4,
            float* __restrict__ out_edge)
{
    extern __shared__ uint2 smem2[];
    uint2* sA = smem2;                   // [64 rows][SA2 kpairs]; aliased as f32 staging
    __shared__ float  sPar[10 * 128];
    __shared__ float2 sPart[MTILE][4];
    __shared__ int    sSrc[MTILE], sDst[MTILE];

    int tid = threadIdx.x;
    int w   = tid >> 5;
    int rb  = (w >> 2) * 32;
    int wn  = w & 3;
    int nb0 = wn * 32;
    size_t ebase = (size_t)blockIdx.x * MTILE;

    if (tid < 128) {
        sPar[0*128+tid] = b1[tid]; sPar[1*128+tid] = g1[tid]; sPar[2*128+tid] = t1[tid];
        sPar[3*128+tid] = b2[tid]; sPar[4*128+tid] = g2[tid]; sPar[5*128+tid] = t2[tid];
        sPar[6*128+tid] = b3[tid]; sPar[7*128+tid] = g3[tid]; sPar[8*128+tid] = t3[tid];
        sPar[9*128+tid] = b4[tid];
    } else if (tid < 128 + MTILE) {
        int r = tid - 128;
        sSrc[r] = edge_index[ebase + r];
        sDst[r] = edge_index[(size_t)NE + ebase + r];
    }
    __syncthreads();

    float acc[2][4][4];
    zero_acc(acc);

    // ---- layer 1: K = 384 in 3 chunks, accumulate in registers
    #pragma unroll 1
    for (int c = 0; c < 3; ++c) {
        #pragma unroll
        for (int i = tid; i < MTILE * 32; i += THREADS) {
            int r = i >> 5, j = i & 31;
            const float* src = (c == 0) ? edge_attr + (ebase + r) * H
                                        : x + (size_t)(c == 1 ? sSrc[r] : sDst[r]) * H;
            float4 v = ((const float4*)src)[j];
            uint2 p0 = splitp(make_float2(v.x, v.y));
            uint2 p1 = splitp(make_float2(v.z, v.w));
            *(uint4*)(sA + r * SA2 + 2 * j) = make_uint4(p0.x, p0.y, p1.x, p1.y);
        }
        __syncthreads();
        gemm64(sA, g_wB + (size_t)c * 8192, acc, rb, nb0);
        __syncthreads();
    }

    // ---- layers 2..4 (chunks 3,4,5)
    #pragma unroll 1
    for (int l = 0; l < 3; ++l) {
        epi_ln(acc, sPar, l, sA, sPart, rb, nb0, wn);
        __syncthreads();
        zero_acc(acc);
        gemm64(sA, g_wB + (size_t)(3 + l) * 8192, acc, rb, nb0);
        __syncthreads();
    }

    // ---- final: + b4 -> staging (aliases sA), residual write + atomic scatter
    epi_final(acc, sPar, (float*)sA, rb, nb0);
    __syncthreads();

    #pragma unroll
    for (int i = tid; i < MTILE * 32; i += THREADS) {
        int r = i >> 5, j = i & 31;
        float4 val = *(float4*)((float*)sA + r * 132 + j * 4);
        size_t e = ebase + r;
        float4 ea = ((const float4*)(edge_attr + e * H))[j];
        float4 o;
        o.x = ea.x + val.x; o.y = ea.y + val.y; o.z = ea.z + val.z; o.w = ea.w + val.w;
        ((float4*)(out_edge + e * H))[j] = o;
        atomicAdd((float4*)(g_agg + (size_t)sDst[r] * H + j * 4), val);
    }
}

// ---------------------------------------------------------------- node kernel
__global__ void __launch_bounds__(THREADS, 2)
node_kernel(const float* __restrict__ x,
            const float* __restrict__ b1, const float* __restrict__ g1, const float* __restrict__ t1,
            const float* __restrict__ b2, const float* __restrict__ g2, const float* __restrict__ t2,
            const float* __restrict__ b3, const float* __restrict__ g3, const float* __restrict__ t3,
            const float* __restrict__ b4,
            float* __restrict__ out_node)
{
    extern __shared__ uint2 smem2[];
    uint2* sA = smem2;
    __shared__ float  sPar[10 * 128];
    __shared__ float2 sPart[MTILE][4];

    int tid = threadIdx.x;
    int w   = tid >> 5;
    int rb  = (w >> 2) * 32;
    int wn  = w & 3;
    int nb0 = wn * 32;
    size_t nbase = (size_t)blockIdx.x * MTILE;

    if (tid < 128) {
        sPar[0*128+tid] = b1[tid]; sPar[1*128+tid] = g1[tid]; sPar[2*128+tid] = t1[tid];
        sPar[3*128+tid] = b2[tid]; sPar[4*128+tid] = g2[tid]; sPar[5*128+tid] = t2[tid];
        sPar[6*128+tid] = b3[tid]; sPar[7*128+tid] = g3[tid]; sPar[8*128+tid] = t3[tid];
        sPar[9*128+tid] = b4[tid];
    }
    __syncthreads();

    float acc[2][4][4];
    zero_acc(acc);

    // ---- layer 1: K = 256 in 2 chunks ([x | agg]); agg re-zeroed after read
    #pragma unroll 1
    for (int c = 0; c < 2; ++c) {
        #pragma unroll
        for (int i = tid; i < MTILE * 32; i += THREADS) {
            int r = i >> 5, j = i & 31;
            size_t node = nbase + r;
            float4 v = make_float4(0.f, 0.f, 0.f, 0.f);
            if (node < NN) {
                if (c == 0) {
                    v = ((const float4*)(x + node * H))[j];
                } else {
                    float4* ap = (float4*)(g_agg + node * H) + j;
                    v = *ap;
                    *ap = make_float4(0.f, 0.f, 0.f, 0.f);  // restore invariant
                }
            }
            uint2 p0 = splitp(make_float2(v.x, v.y));
            uint2 p1 = splitp(make_float2(v.z, v.w));
            *(uint4*)(sA + r * SA2 + 2 * j) = make_uint4(p0.x, p0.y, p1.x, p1.y);
        }
        __syncthreads();
        gemm64(sA, g_wB + (size_t)(6 + c) * 8192, acc, rb, nb0);
        __syncthreads();
    }

    // ---- layers 2..4 (chunks 8,9,10)
    #pragma unroll 1
    for (int l = 0; l < 3; ++l) {
        epi_ln(acc, sPar, l, sA, sPart, rb, nb0, wn);
        __syncthreads();
        zero_acc(acc);
        gemm64(sA, g_wB + (size_t)(8 + l) * 8192, acc, rb, nb0);
        __syncthreads();
    }

    epi_final(acc, sPar, (float*)sA, rb, nb0);
    __syncthreads();

    #pragma unroll
    for (int i = tid; i < MTILE * 32; i += THREADS) {
        int r = i >> 5, j = i & 31;
        size_t node = nbase + r;
        if (node < NN) {
            float4 val = *(float4*)((float*)sA + r * 132 + j * 4);
            float4 xv = ((const float4*)(x + node * H))[j];
            float4 o;
            o.x = xv.x + val.x; o.y = xv.y + val.y; o.z = xv.z + val.z; o.w = xv.w + val.w;
            ((float4*)(out_node + node * H))[j] = o;
        }
    }
}

// ---------------------------------------------------------------- launch
extern "C" void kernel_launch(void* const* d_in, const int* in_sizes, int n_in,
                              void* d_out, int out_size)
{
    const float* x          = (const float*)d_in[0];
    const float* edge_attr  = (const float*)d_in[1];
    const int*   edge_index = (const int*)d_in[2];

    const float* eW1 = (const float*)d_in[3];  const float* eb1 = (const float*)d_in[4];
    const float* eW2 = (const float*)d_in[5];  const float* eb2 = (const float*)d_in[6];
    const float* eW3 = (const float*)d_in[7];  const float* eb3 = (const float*)d_in[8];
    const float* eW4 = (const float*)d_in[9];  const float* eb4 = (const float*)d_in[10];
    const float* eg1 = (const float*)d_in[11]; const float* et1 = (const float*)d_in[12];
    const float* eg2 = (const float*)d_in[13]; const float* et2 = (const float*)d_in[14];
    const float* eg3 = (const float*)d_in[15]; const float* et3 = (const float*)d_in[16];

    const float* nW1 = (const float*)d_in[17]; const float* nb1 = (const float*)d_in[18];
    const float* nW2 = (const float*)d_in[19]; const float* nb2 = (const float*)d_in[20];
    const float* nW3 = (const float*)d_in[21]; const float* nb3 = (const float*)d_in[22];
    const float* nW4 = (const float*)d_in[23]; const float* nb4 = (const float*)d_in[24];
    const float* ng1 = (const float*)d_in[25]; const float* nt1 = (const float*)d_in[26];
    const float* ng2 = (const float*)d_in[27]; const float* nt2 = (const float*)d_in[28];
    const float* ng3 = (const float*)d_in[29]; const float* nt3 = (const float*)d_in[30];

    float* out_node = (float*)d_out;                   // [NN*H]
    float* out_edge = (float*)d_out + (size_t)NN * H;  // [NE*H]

    const int SMEM = MTILE * SA2 * 8;  // 34816 B
    cudaFuncSetAttribute(edge_kernel, cudaFuncAttributeMaxDynamicSharedMemorySize, SMEM);
    cudaFuncSetAttribute(node_kernel, cudaFuncAttributeMaxDynamicSharedMemorySize, SMEM);

    wprep_kernel<<<(11 * 8192 + 255) / 256, 256>>>(eW1, eW2, eW3, eW4,
                                                   nW1, nW2, nW3, nW4);

    edge_kernel<<<NE / MTILE, THREADS, SMEM>>>(
        x, edge_attr, edge_index,
        eb1, eg1, et1, eb2, eg2, et2, eb3, eg3, et3, eb4,
        out_edge);

    node_kernel<<<(NN + MTILE - 1) / MTILE, THREADS, SMEM>>>(
        x,
        nb1, ng1, nt1, nb2, ng2, nt2, nb3, ng3, nt3, nb4,
        out_node);
}

// round 11
// speedup vs baseline: 1.0957x; 1.0957x over previous
#include <cuda_runtime.h>
#include <cuda_bf16.h>
#include <cstdint>

#define H        128
#define NE       400000
#define NN       50000
#define THREADS  256
#define MTILE    64
#define SA2      68    // uint2 stride for A kpairs (mod 16 == 4 -> conflict-free)

// scatter-add accumulator; zero-initialized at module load, re-zeroed by
// node_kernel after consumption -> invariant: zero at start of every launch.
__device__ float g_agg[NN * H];
// prepacked split-bf16 weights: 11 chunks x [64 kpairs][128 cols] uint2(hi,lo)
__device__ uint2 g_wB[11 * 8192];

// ---------------------------------------------------------------- helpers
__device__ __forceinline__ void split2(float2 v, uint32_t& hi, uint32_t& lo) {
    __nv_bfloat162 h = __float22bfloat162_rn(v);
    float2 hf = __bfloat1622float2(h);
    __nv_bfloat162 l = __float22bfloat162_rn(make_float2(v.x - hf.x, v.y - hf.y));
    hi = *(uint32_t*)&h;
    lo = *(uint32_t*)&l;
}
__device__ __forceinline__ uint2 splitp(float2 v) {
    uint2 r; split2(v, r.x, r.y); return r;
}

__device__ __forceinline__ void mma_bf16(float d[4], const uint32_t a[4],
                                         uint32_t b0, uint32_t b1) {
    asm volatile(
        "mma.sync.aligned.m16n8k16.row.col.f32.bf16.bf16.f32 "
        "{%0,%1,%2,%3}, {%4,%5,%6,%7}, {%8,%9}, {%0,%1,%2,%3};"
        : "+f"(d[0]), "+f"(d[1]), "+f"(d[2]), "+f"(d[3])
        : "r"(a[0]), "r"(a[1]), "r"(a[2]), "r"(a[3]), "r"(b0), "r"(b1));
}

// ---------------------------------------------------------------- wprep
// Pack all weight chunks once: g_wB[chunk*8192 + kp*128 + col] = split(W[2kp..2kp+1][col])
// chunks: 0-2 eW1(k0=0,128,256), 3 eW2, 4 eW3, 5 eW4, 6-7 nW1(k0=0,128), 8 nW2, 9 nW3, 10 nW4
__global__ void wprep_kernel(const float* __restrict__ eW1, const float* __restrict__ eW2,
                             const float* __restrict__ eW3, const float* __restrict__ eW4,
                             const float* __restrict__ nW1, const float* __restrict__ nW2,
                             const float* __restrict__ nW3, const float* __restrict__ nW4)
{
    int i = blockIdx.x * blockDim.x + threadIdx.x;
    if (i >= 11 * 8192) return;
    int chunk = i >> 13, e = i & 8191;
    int kp = e >> 7, col = e & 127;
    const float* W; int k0;
    switch (chunk) {
        case 0:  W = eW1; k0 = 0;   break;
        case 1:  W = eW1; k0 = 128; break;
        case 2:  W = eW1; k0 = 256; break;
        case 3:  W = eW2; k0 = 0;   break;
        case 4:  W = eW3; k0 = 0;   break;
        case 5:  W = eW4; k0 = 0;   break;
        case 6:  W = nW1; k0 = 0;   break;
        case 7:  W = nW1; k0 = 128; break;
        case 8:  W = nW2; k0 = 0;   break;
        case 9:  W = nW3; k0 = 0;   break;
        default: W = nW4; k0 = 0;   break;
    }
    float2 v = make_float2(W[(size_t)(k0 + 2 * kp)     * H + col],
                           W[(size_t)(k0 + 2 * kp + 1) * H + col]);
    g_wB[i] = splitp(v);
}

// ---------------------------------------------------------------- gemm
// Warp tile m32 x n32: rows rb..rb+31, scalar cols nb0..nb0+31.
// A from smem (split uint2 per kpair); B fragments from prepacked global
// chunk (L1/L2-hot). Split-bf16 terms issued GROUPED so each accumulator's
// RAW reuse distance is 8 independent HMMAs (was 1 -> dependency stalls).
__device__ __forceinline__ void gemm64(const uint2* sA, const uint2* __restrict__ gB,
                                       float acc[2][4][4], int rb, int nb0) {
    int lane = threadIdx.x & 31;
    int gid  = lane >> 2, tig = lane & 3;
    const uint2* A0 = sA + (rb + gid) * SA2;
    #pragma unroll 1
    for (int ks = 0; ks < 8; ++ks) {
        int kp = ks * 8 + tig;
        uint32_t ah[2][4], al[2][4];
        #pragma unroll
        for (int mb = 0; mb < 2; ++mb) {
            const uint2* Ar0 = A0 + mb * 16 * SA2 + kp;
            const uint2* Ar8 = Ar0 + 8 * SA2;
            uint2 q0 = Ar0[0], q1 = Ar8[0], q2 = Ar0[4], q3 = Ar8[4];
            ah[mb][0] = q0.x; al[mb][0] = q0.y;
            ah[mb][1] = q1.x; al[mb][1] = q1.y;
            ah[mb][2] = q2.x; al[mb][2] = q2.y;
            ah[mb][3] = q3.x; al[mb][3] = q3.y;
        }
        const uint2* Bp0 = gB + kp * 128 + nb0 + gid;
        const uint2* Bp1 = Bp0 + 4 * 128;
        uint2 b0[4], b1[4];
        #pragma unroll
        for (int nt = 0; nt < 4; ++nt) {
            b0[nt] = __ldg(Bp0 + nt * 8);
            b1[nt] = __ldg(Bp1 + nt * 8);
        }
        // term 1: A_hi * B_hi  (8 independent MMAs)
        #pragma unroll
        for (int nt = 0; nt < 4; ++nt)
            #pragma unroll
            for (int mb = 0; mb < 2; ++mb)
                mma_bf16(acc[mb][nt], ah[mb], b0[nt].x, b1[nt].x);
        // term 2: A_lo * B_hi
        #pragma unroll
        for (int nt = 0; nt < 4; ++nt)
            #pragma unroll
            for (int mb = 0; mb < 2; ++mb)
                mma_bf16(acc[mb][nt], al[mb], b0[nt].x, b1[nt].x);
        // term 3: A_hi * B_lo
        #pragma unroll
        for (int nt = 0; nt < 4; ++nt)
            #pragma unroll
            for (int mb = 0; mb < 2; ++mb)
                mma_bf16(acc[mb][nt], ah[mb], b0[nt].y, b1[nt].y);
    }
}

__device__ __forceinline__ void zero_acc(float acc[2][4][4]) {
    #pragma unroll
    for (int mb = 0; mb < 2; ++mb)
        #pragma unroll
        for (int nt = 0; nt < 4; ++nt)
            #pragma unroll
            for (int c = 0; c < 4; ++c) acc[mb][nt][c] = 0.0f;
}

// bias + ReLU + LayerNorm (rows split across 4 n-warps); split-store into sA
__device__ __forceinline__ void epi_ln(float acc[2][4][4], const float* sPar, int l,
                                       uint2* sA, float2 (*sPart)[4], int rb, int nb0,
                                       int wn) {
    int lane = threadIdx.x & 31;
    int gid  = lane >> 2, tig = lane & 3;
    const float* bb = sPar + l * 3 * 128;
    const float* gg = bb + 128;
    const float* tt = bb + 256;
    float s[4] = {0.f, 0.f, 0.f, 0.f}, s2[4] = {0.f, 0.f, 0.f, 0.f};
    #pragma unroll
    for (int mb = 0; mb < 2; ++mb)
        #pragma unroll
        for (int nt = 0; nt < 4; ++nt) {
            int col = nb0 + nt * 8 + 2 * tig;
            float2 b = *(const float2*)(bb + col);
            float t0 = fmaxf(acc[mb][nt][0] + b.x, 0.f);
            float t1 = fmaxf(acc[mb][nt][1] + b.y, 0.f);
            float t2 = fmaxf(acc[mb][nt][2] + b.x, 0.f);
            float t3 = fmaxf(acc[mb][nt][3] + b.y, 0.f);
            acc[mb][nt][0] = t0; acc[mb][nt][1] = t1;
            acc[mb][nt][2] = t2; acc[mb][nt][3] = t3;
            s[2*mb]   += t0 + t1; s2[2*mb]   = fmaf(t0, t0, fmaf(t1, t1, s2[2*mb]));
            s[2*mb+1] += t2 + t3; s2[2*mb+1] = fmaf(t2, t2, fmaf(t3, t3, s2[2*mb+1]));
        }
    #pragma unroll
    for (int m = 1; m <= 2; m <<= 1)
        #pragma unroll
        for (int k = 0; k < 4; ++k) {
            s[k]  += __shfl_xor_sync(0xffffffffu, s[k],  m);
            s2[k] += __shfl_xor_sync(0xffffffffu, s2[k], m);
        }
    int R[4] = {rb + gid, rb + gid + 8, rb + 16 + gid, rb + 24 + gid};
    if (tig == 0) {
        #pragma unroll
        for (int k = 0; k < 4; ++k) sPart[R[k]][wn] = make_float2(s[k], s2[k]);
    }
    __syncthreads();
    float mean[4], inv[4];
    #pragma unroll
    for (int k = 0; k < 4; ++k) {
        float2 p0 = sPart[R[k]][0], p1 = sPart[R[k]][1];
        float2 p2 = sPart[R[k]][2], p3 = sPart[R[k]][3];
        float sm = (p0.x + p1.x) + (p2.x + p3.x);
        float sq = (p0.y + p1.y) + (p2.y + p3.y);
        mean[k] = sm * 0.0078125f;
        inv[k]  = rsqrtf(fmaf(-mean[k], mean[k], sq * 0.0078125f) + 1e-5f);
    }
    #pragma unroll
    for (int mb = 0; mb < 2; ++mb)
        #pragma unroll
        for (int nt = 0; nt < 4; ++nt) {
            int col = nb0 + nt * 8 + 2 * tig;
            int kpo = col >> 1;
            float2 g = *(const float2*)(gg + col);
            float2 t = *(const float2*)(tt + col);
            float2 va, vb;
            va.x = fmaf((acc[mb][nt][0] - mean[2*mb]) * inv[2*mb], g.x, t.x);
            va.y = fmaf((acc[mb][nt][1] - mean[2*mb]) * inv[2*mb], g.y, t.y);
            vb.x = fmaf((acc[mb][nt][2] - mean[2*mb+1]) * inv[2*mb+1], g.x, t.x);
            vb.y = fmaf((acc[mb][nt][3] - mean[2*mb+1]) * inv[2*mb+1], g.y, t.y);
            sA[R[2*mb]   * SA2 + kpo] = splitp(va);
            sA[R[2*mb+1] * SA2 + kpo] = splitp(vb);
        }
}

// final layer: acc + b4 -> f32 staging (stride 132 floats; ALIASES sA)
__device__ __forceinline__ void epi_final(float acc[2][4][4], const float* sPar,
                                          float* sC, int rb, int nb0) {
    int lane = threadIdx.x & 31;
    int gid  = lane >> 2, tig = lane & 3;
    const float* b4 = sPar + 9 * 128;
    #pragma unroll
    for (int mb = 0; mb < 2; ++mb) {
        int r0 = rb + mb * 16 + gid;
        #pragma unroll
        for (int nt = 0; nt < 4; ++nt) {
            int col = nb0 + nt * 8 + 2 * tig;
            float2 b = *(const float2*)(b4 + col);
            float2 va, vb;
            va.x = acc[mb][nt][0] + b.x; va.y = acc[mb][nt][1] + b.y;
            vb.x = acc[mb][nt][2] + b.x; vb.y = acc[mb][nt][3] + b.y;
            *(float2*)(sC + r0 * 132 + col)       = va;
            *(float2*)(sC + (r0 + 8) * 132 + col) = vb;
        }
    }
}

// ---------------------------------------------------------------- edge kernel
__global__ void __launch_bounds__(THREADS, 2)
edge_kernel(const float* __restrict__ x, const float* __restrict__ edge_attr,
            const int* __restrict__ edge_index,
            const float* __restrict__ b1, const float* __restrict__ g1, const float* __restrict__ t1,
            const float* __restrict__ b2, const float* __restrict__ g2, const float* __restrict__ t2,
            const float* __restrict__ b3, const float* __restrict__ g3, const float* __restrict__ t3,
            const float* __restrict__ b4,
            float* __restrict__ out_edge)
{
    extern __shared__ uint2 smem2[];
    uint2* sA = smem2;                   // [64 rows][SA2 kpairs]; aliased as f32 staging
    __shared__ float  sPar[10 * 128];
    __shared__ float2 sPart[MTILE][4];
    __shared__ int    sSrc[MTILE], sDst[MTILE];

    int tid = threadIdx.x;
    int w   = tid >> 5;
    int rb  = (w >> 2) * 32;
    int wn  = w & 3;
    int nb0 = wn * 32;
    size_t ebase = (size_t)blockIdx.x * MTILE;

    if (tid < 128) {
        sPar[0*128+tid] = b1[tid]; sPar[1*128+tid] = g1[tid]; sPar[2*128+tid] = t1[tid];
        sPar[3*128+tid] = b2[tid]; sPar[4*128+tid] = g2[tid]; sPar[5*128+tid] = t2[tid];
        sPar[6*128+tid] = b3[tid]; sPar[7*128+tid] = g3[tid]; sPar[8*128+tid] = t3[tid];
        sPar[9*128+tid] = b4[tid];
    } else if (tid < 128 + MTILE) {
        int r = tid - 128;
        sSrc[r] = edge_index[ebase + r];
        sDst[r] = edge_index[(size_t)NE + ebase + r];
    }
    __syncthreads();

    float acc[2][4][4];
    zero_acc(acc);

    // ---- layer 1: K = 384 in 3 chunks, accumulate in registers
    #pragma unroll 1
    for (int c = 0; c < 3; ++c) {
        #pragma unroll
        for (int i = tid; i < MTILE * 32; i += THREADS) {
            int r = i >> 5, j = i & 31;
            const float* src = (c == 0) ? edge_attr + (ebase + r) * H
                                        : x + (size_t)(c == 1 ? sSrc[r] : sDst[r]) * H;
            float4 v = ((const float4*)src)[j];
            uint2 p0 = splitp(make_float2(v.x, v.y));
            uint2 p1 = splitp(make_float2(v.z, v.w));
            *(uint4*)(sA + r * SA2 + 2 * j) = make_uint4(p0.x, p0.y, p1.x, p1.y);
        }
        __syncthreads();
        gemm64(sA, g_wB + (size_t)c * 8192, acc, rb, nb0);
        __syncthreads();
    }

    // ---- layers 2..4 (chunks 3,4,5)
    #pragma unroll 1
    for (int l = 0; l < 3; ++l) {
        epi_ln(acc, sPar, l, sA, sPart, rb, nb0, wn);
        __syncthreads();
        zero_acc(acc);
        gemm64(sA, g_wB + (size_t)(3 + l) * 8192, acc, rb, nb0);
        __syncthreads();
    }

    // ---- final: + b4 -> staging (aliases sA), residual write + atomic scatter
    epi_final(acc, sPar, (float*)sA, rb, nb0);
    __syncthreads();

    #pragma unroll
    for (int i = tid; i < MTILE * 32; i += THREADS) {
        int r = i >> 5, j = i & 31;
        float4 val = *(float4*)((float*)sA + r * 132 + j * 4);
        size_t e = ebase + r;
        float4 ea = ((const float4*)(edge_attr + e * H))[j];
        float4 o;
        o.x = ea.x + val.x; o.y = ea.y + val.y; o.z = ea.z + val.z; o.w = ea.w + val.w;
        ((float4*)(out_edge + e * H))[j] = o;
        atomicAdd((float4*)(g_agg + (size_t)sDst[r] * H + j * 4), val);
    }
}

// ---------------------------------------------------------------- node kernel
__global__ void __launch_bounds__(THREADS, 2)
node_kernel(const float* __restrict__ x,
            const float* __restrict__ b1, const float* __restrict__ g1, const float* __restrict__ t1,
            const float* __restrict__ b2, const float* __restrict__ g2, const float* __restrict__ t2,
            const float* __restrict__ b3, const float* __restrict__ g3, const float* __restrict__ t3,
            const float* __restrict__ b4,
            float* __restrict__ out_node)
{
    extern __shared__ uint2 smem2[];
    uint2* sA = smem2;
    __shared__ float  sPar[10 * 128];
    __shared__ float2 sPart[MTILE][4];

    int tid = threadIdx.x;
    int w   = tid >> 5;
    int rb  = (w >> 2) * 32;
    int wn  = w & 3;
    int nb0 = wn * 32;
    size_t nbase = (size_t)blockIdx.x * MTILE;

    if (tid < 128) {
        sPar[0*128+tid] = b1[tid]; sPar[1*128+tid] = g1[tid]; sPar[2*128+tid] = t1[tid];
        sPar[3*128+tid] = b2[tid]; sPar[4*128+tid] = g2[tid]; sPar[5*128+tid] = t2[tid];
        sPar[6*128+tid] = b3[tid]; sPar[7*128+tid] = g3[tid]; sPar[8*128+tid] = t3[tid];
        sPar[9*128+tid] = b4[tid];
    }
    __syncthreads();

    float acc[2][4][4];
    zero_acc(acc);

    // ---- layer 1: K = 256 in 2 chunks ([x | agg]); agg re-zeroed after read
    #pragma unroll 1
    for (int c = 0; c < 2; ++c) {
        #pragma unroll
        for (int i = tid; i < MTILE * 32; i += THREADS) {
            int r = i >> 5, j = i & 31;
            size_t node = nbase + r;
            float4 v = make_float4(0.f, 0.f, 0.f, 0.f);
            if (node < NN) {
                if (c == 0) {
                    v = ((const float4*)(x + node * H))[j];
                } else {
                    float4* ap = (float4*)(g_agg + node * H) + j;
                    v = *ap;
                    *ap = make_float4(0.f, 0.f, 0.f, 0.f);  // restore invariant
                }
            }
            uint2 p0 = splitp(make_float2(v.x, v.y));
            uint2 p1 = splitp(make_float2(v.z, v.w));
            *(uint4*)(sA + r * SA2 + 2 * j) = make_uint4(p0.x, p0.y, p1.x, p1.y);
        }
        __syncthreads();
        gemm64(sA, g_wB + (size_t)(6 + c) * 8192, acc, rb, nb0);
        __syncthreads();
    }

    // ---- layers 2..4 (chunks 8,9,10)
    #pragma unroll 1
    for (int l = 0; l < 3; ++l) {
        epi_ln(acc, sPar, l, sA, sPart, rb, nb0, wn);
        __syncthreads();
        zero_acc(acc);
        gemm64(sA, g_wB + (size_t)(8 + l) * 8192, acc, rb, nb0);
        __syncthreads();
    }

    epi_final(acc, sPar, (float*)sA, rb, nb0);
    __syncthreads();

    #pragma unroll
    for (int i = tid; i < MTILE * 32; i += THREADS) {
        int r = i >> 5, j = i & 31;
        size_t node = nbase + r;
        if (node < NN) {
            float4 val = *(float4*)((float*)sA + r * 132 + j * 4);
            float4 xv = ((const float4*)(x + node * H))[j];
            float4 o;
            o.x = xv.x + val.x; o.y = xv.y + val.y; o.z = xv.z + val.z; o.w = xv.w + val.w;
            ((float4*)(out_node + node * H))[j] = o;
        }
    }
}

// ---------------------------------------------------------------- launch
extern "C" void kernel_launch(void* const* d_in, const int* in_sizes, int n_in,
                              void* d_out, int out_size)
{
    const float* x          = (const float*)d_in[0];
    const float* edge_attr  = (const float*)d_in[1];
    const int*   edge_index = (const int*)d_in[2];

    const float* eW1 = (const float*)d_in[3];  const float* eb1 = (const float*)d_in[4];
    const float* eW2 = (const float*)d_in[5];  const float* eb2 = (const float*)d_in[6];
    const float* eW3 = (const float*)d_in[7];  const float* eb3 = (const float*)d_in[8];
    const float* eW4 = (const float*)d_in[9];  const float* eb4 = (const float*)d_in[10];
    const float* eg1 = (const float*)d_in[11]; const float* et1 = (const float*)d_in[12];
    const float* eg2 = (const float*)d_in[13]; const float* et2 = (const float*)d_in[14];
    const float* eg3 = (const float*)d_in[15]; const float* et3 = (const float*)d_in[16];

    const float* nW1 = (const float*)d_in[17]; const float* nb1 = (const float*)d_in[18];
    const float* nW2 = (const float*)d_in[19]; const float* nb2 = (const float*)d_in[20];
    const float* nW3 = (const float*)d_in[21]; const float* nb3 = (const float*)d_in[22];
    const float* nW4 = (const float*)d_in[23]; const float* nb4 = (const float*)d_in[24];
    const float* ng1 = (const float*)d_in[25]; const float* nt1 = (const float*)d_in[26];
    const float* ng2 = (const float*)d_in[27]; const float* nt2 = (const float*)d_in[28];
    const float* ng3 = (const float*)d_in[29]; const float* nt3 = (const float*)d_in[30];

    float* out_node = (float*)d_out;                   // [NN*H]
    float* out_edge = (float*)d_out + (size_t)NN * H;  // [NE*H]

    const int SMEM = MTILE * SA2 * 8;  // 34816 B
    cudaFuncSetAttribute(edge_kernel, cudaFuncAttributeMaxDynamicSharedMemorySize, SMEM);
    cudaFuncSetAttribute(node_kernel, cudaFuncAttributeMaxDynamicSharedMemorySize, SMEM);

    wprep_kernel<<<(11 * 8192 + 255) / 256, 256>>>(eW1, eW2, eW3, eW4,
                                                   nW1, nW2, nW3, nW4);

    edge_kernel<<<NE / MTILE, THREADS, SMEM>>>(
        x, edge_attr, edge_index,
        eb1, eg1, et1, eb2, eg2, et2, eb3, eg3, et3, eb4,
        out_edge);

    node_kernel<<<(NN + MTILE - 1) / MTILE, THREADS, SMEM>>>(
        x,
        nb1, ng1, nt1, nb2, ng2, nt2, nb3, ng3, nt3, nb4,
        out_node);
}

// round 12
// speedup vs baseline: 1.1764x; 1.0736x over previous
#include <cuda_runtime.h>
#include <cuda_bf16.h>
#include <cstdint>

#define H        128
#define NE       400000
#define NN       50000
#define THREADS  256
#define MTILE    64
#define SA2      68    // uint2 stride for A kpairs (mod 16 == 4 -> conflict-free)

// scatter-add accumulator; zero-initialized at module load, re-zeroed by
// node_kernel after consumption -> invariant: zero at start of every launch.
__device__ float g_agg[NN * H];
// prepacked split-bf16 weights: 11 chunks x [64 kpairs][128 cols] uint2(hi,lo)
__device__ uint2 g_wB[11 * 8192];

// ---------------------------------------------------------------- helpers
__device__ __forceinline__ void split2(float2 v, uint32_t& hi, uint32_t& lo) {
    __nv_bfloat162 h = __float22bfloat162_rn(v);
    float2 hf = __bfloat1622float2(h);
    __nv_bfloat162 l = __float22bfloat162_rn(make_float2(v.x - hf.x, v.y - hf.y));
    hi = *(uint32_t*)&h;
    lo = *(uint32_t*)&l;
}
__device__ __forceinline__ uint2 splitp(float2 v) {
    uint2 r; split2(v, r.x, r.y); return r;
}

__device__ __forceinline__ void mma_bf16(float d[4], const uint32_t a[4],
                                         uint32_t b0, uint32_t b1) {
    asm volatile(
        "mma.sync.aligned.m16n8k16.row.col.f32.bf16.bf16.f32 "
        "{%0,%1,%2,%3}, {%4,%5,%6,%7}, {%8,%9}, {%0,%1,%2,%3};"
        : "+f"(d[0]), "+f"(d[1]), "+f"(d[2]), "+f"(d[3])
        : "r"(a[0]), "r"(a[1]), "r"(a[2]), "r"(a[3]), "r"(b0), "r"(b1));
}

// ---------------------------------------------------------------- wprep
// Pack all weight chunks once: g_wB[chunk*8192 + kp*128 + col] = split(W[2kp..2kp+1][col])
// chunks: 0-2 eW1(k0=0,128,256), 3 eW2, 4 eW3, 5 eW4, 6-7 nW1(k0=0,128), 8 nW2, 9 nW3, 10 nW4
__global__ void wprep_kernel(const float* __restrict__ eW1, const float* __restrict__ eW2,
                             const float* __restrict__ eW3, const float* __restrict__ eW4,
                             const float* __restrict__ nW1, const float* __restrict__ nW2,
                             const float* __restrict__ nW3, const float* __restrict__ nW4)
{
    int i = blockIdx.x * blockDim.x + threadIdx.x;
    if (i >= 11 * 8192) return;
    int chunk = i >> 13, e = i & 8191;
    int kp = e >> 7, col = e & 127;
    const float* W; int k0;
    switch (chunk) {
        case 0:  W = eW1; k0 = 0;   break;
        case 1:  W = eW1; k0 = 128; break;
        case 2:  W = eW1; k0 = 256; break;
        case 3:  W = eW2; k0 = 0;   break;
        case 4:  W = eW3; k0 = 0;   break;
        case 5:  W = eW4; k0 = 0;   break;
        case 6:  W = nW1; k0 = 0;   break;
        case 7:  W = nW1; k0 = 128; break;
        case 8:  W = nW2; k0 = 0;   break;
        case 9:  W = nW3; k0 = 0;   break;
        default: W = nW4; k0 = 0;   break;
    }
    float2 v = make_float2(W[(size_t)(k0 + 2 * kp)     * H + col],
                           W[(size_t)(k0 + 2 * kp + 1) * H + col]);
    g_wB[i] = splitp(v);
}

// ---------------------------------------------------------------- gemm
// Warp tile m32 x n32, rows rb..rb+31, scalar cols nb0..nb0+31.
// Software-pipelined over ksteps: fragments for kstep i+1 are loaded (LDS for A,
// LDG for B) BEFORE kstep i's 24 MMAs issue, hiding load latency behind the
// tensor-pipe window. MMA terms grouped so acc RAW reuse distance stays 8.
struct Frag {
    uint32_t ah[2][4], al[2][4];
    uint2    b0[4],    b1[4];
};

__device__ __forceinline__ void load_frag(Frag& f, const uint2* A0,
                                          const uint2* __restrict__ gB,
                                          int kp, int nb0, int gid) {
    #pragma unroll
    for (int mb = 0; mb < 2; ++mb) {
        const uint2* Ar0 = A0 + mb * 16 * SA2 + kp;
        const uint2* Ar8 = Ar0 + 8 * SA2;
        uint2 q0 = Ar0[0], q1 = Ar8[0], q2 = Ar0[4], q3 = Ar8[4];
        f.ah[mb][0] = q0.x; f.al[mb][0] = q0.y;
        f.ah[mb][1] = q1.x; f.al[mb][1] = q1.y;
        f.ah[mb][2] = q2.x; f.al[mb][2] = q2.y;
        f.ah[mb][3] = q3.x; f.al[mb][3] = q3.y;
    }
    const uint2* Bp0 = gB + kp * 128 + nb0 + gid;
    const uint2* Bp1 = Bp0 + 4 * 128;
    #pragma unroll
    for (int nt = 0; nt < 4; ++nt) {
        f.b0[nt] = __ldg(Bp0 + nt * 8);
        f.b1[nt] = __ldg(Bp1 + nt * 8);
    }
}

__device__ __forceinline__ void mma_frag(const Frag& f, float acc[2][4][4]) {
    // term 1: A_hi * B_hi (8 independent MMAs)
    #pragma unroll
    for (int nt = 0; nt < 4; ++nt)
        #pragma unroll
        for (int mb = 0; mb < 2; ++mb)
            mma_bf16(acc[mb][nt], f.ah[mb], f.b0[nt].x, f.b1[nt].x);
    // term 2: A_lo * B_hi
    #pragma unroll
    for (int nt = 0; nt < 4; ++nt)
        #pragma unroll
        for (int mb = 0; mb < 2; ++mb)
            mma_bf16(acc[mb][nt], f.al[mb], f.b0[nt].x, f.b1[nt].x);
    // term 3: A_hi * B_lo
    #pragma unroll
    for (int nt = 0; nt < 4; ++nt)
        #pragma unroll
        for (int mb = 0; mb < 2; ++mb)
            mma_bf16(acc[mb][nt], f.ah[mb], f.b0[nt].y, f.b1[nt].y);
}

__device__ __forceinline__ void gemm64(const uint2* sA, const uint2* __restrict__ gB,
                                       float acc[2][4][4], int rb, int nb0) {
    int lane = threadIdx.x & 31;
    int gid  = lane >> 2, tig = lane & 3;
    const uint2* A0 = sA + (rb + gid) * SA2;
    Frag fa, fb;
    load_frag(fa, A0, gB, tig, nb0, gid);
    #pragma unroll
    for (int ks = 0; ks < 8; ++ks) {
        if (ks & 1) {
            if (ks < 7) load_frag(fa, A0, gB, (ks + 1) * 8 + tig, nb0, gid);
            mma_frag(fb, acc);
        } else {
            if (ks < 7) load_frag(fb, A0, gB, (ks + 1) * 8 + tig, nb0, gid);
            mma_frag(fa, acc);
        }
    }
}

__device__ __forceinline__ void zero_acc(float acc[2][4][4]) {
    #pragma unroll
    for (int mb = 0; mb < 2; ++mb)
        #pragma unroll
        for (int nt = 0; nt < 4; ++nt)
            #pragma unroll
            for (int c = 0; c < 4; ++c) acc[mb][nt][c] = 0.0f;
}

// bias + ReLU + LayerNorm (rows split across 4 n-warps); split-store into sA
__device__ __forceinline__ void epi_ln(float acc[2][4][4], const float* sPar, int l,
                                       uint2* sA, float2 (*sPart)[4], int rb, int nb0,
                                       int wn) {
    int lane = threadIdx.x & 31;
    int gid  = lane >> 2, tig = lane & 3;
    const float* bb = sPar + l * 3 * 128;
    const float* gg = bb + 128;
    const float* tt = bb + 256;
    float s[4] = {0.f, 0.f, 0.f, 0.f}, s2[4] = {0.f, 0.f, 0.f, 0.f};
    #pragma unroll
    for (int mb = 0; mb < 2; ++mb)
        #pragma unroll
        for (int nt = 0; nt < 4; ++nt) {
            int col = nb0 + nt * 8 + 2 * tig;
            float2 b = *(const float2*)(bb + col);
            float t0 = fmaxf(acc[mb][nt][0] + b.x, 0.f);
            float t1 = fmaxf(acc[mb][nt][1] + b.y, 0.f);
            float t2 = fmaxf(acc[mb][nt][2] + b.x, 0.f);
            float t3 = fmaxf(acc[mb][nt][3] + b.y, 0.f);
            acc[mb][nt][0] = t0; acc[mb][nt][1] = t1;
            acc[mb][nt][2] = t2; acc[mb][nt][3] = t3;
            s[2*mb]   += t0 + t1; s2[2*mb]   = fmaf(t0, t0, fmaf(t1, t1, s2[2*mb]));
            s[2*mb+1] += t2 + t3; s2[2*mb+1] = fmaf(t2, t2, fmaf(t3, t3, s2[2*mb+1]));
        }
    #pragma unroll
    for (int m = 1; m <= 2; m <<= 1)
        #pragma unroll
        for (int k = 0; k < 4; ++k) {
            s[k]  += __shfl_xor_sync(0xffffffffu, s[k],  m);
            s2[k] += __shfl_xor_sync(0xffffffffu, s2[k], m);
        }
    int R[4] = {rb + gid, rb + gid + 8, rb + 16 + gid, rb + 24 + gid};
    if (tig == 0) {
        #pragma unroll
        for (int k = 0; k < 4; ++k) sPart[R[k]][wn] = make_float2(s[k], s2[k]);
    }
    __syncthreads();
    float mean[4], inv[4];
    #pragma unroll
    for (int k = 0; k < 4; ++k) {
        float2 p0 = sPart[R[k]][0], p1 = sPart[R[k]][1];
        float2 p2 = sPart[R[k]][2], p3 = sPart[R[k]][3];
        float sm = (p0.x + p1.x) + (p2.x + p3.x);
        float sq = (p0.y + p1.y) + (p2.y + p3.y);
        mean[k] = sm * 0.0078125f;
        inv[k]  = rsqrtf(fmaf(-mean[k], mean[k], sq * 0.0078125f) + 1e-5f);
    }
    #pragma unroll
    for (int mb = 0; mb < 2; ++mb)
        #pragma unroll
        for (int nt = 0; nt < 4; ++nt) {
            int col = nb0 + nt * 8 + 2 * tig;
            int kpo = col >> 1;
            float2 g = *(const float2*)(gg + col);
            float2 t = *(const float2*)(tt + col);
            float2 va, vb;
            va.x = fmaf((acc[mb][nt][0] - mean[2*mb]) * inv[2*mb], g.x, t.x);
            va.y = fmaf((acc[mb][nt][1] - mean[2*mb]) * inv[2*mb], g.y, t.y);
            vb.x = fmaf((acc[mb][nt][2] - mean[2*mb+1]) * inv[2*mb+1], g.x, t.x);
            vb.y = fmaf((acc[mb][nt][3] - mean[2*mb+1]) * inv[2*mb+1], g.y, t.y);
            sA[R[2*mb]   * SA2 + kpo] = splitp(va);
            sA[R[2*mb+1] * SA2 + kpo] = splitp(vb);
        }
}

// final layer: acc + b4 -> f32 staging (stride 132 floats; ALIASES sA)
__device__ __forceinline__ void epi_final(float acc[2][4][4], const float* sPar,
                                          float* sC, int rb, int nb0) {
    int lane = threadIdx.x & 31;
    int gid  = lane >> 2, tig = lane & 3;
    const float* b4 = sPar + 9 * 128;
    #pragma unroll
    for (int mb = 0; mb < 2; ++mb) {
        int r0 = rb + mb * 16 + gid;
        #pragma unroll
        for (int nt = 0; nt < 4; ++nt) {
            int col = nb0 + nt * 8 + 2 * tig;
            float2 b = *(const float2*)(b4 + col);
            float2 va, vb;
            va.x = acc[mb][nt][0] + b.x; va.y = acc[mb][nt][1] + b.y;
            vb.x = acc[mb][nt][2] + b.x; vb.y = acc[mb][nt][3] + b.y;
            *(float2*)(sC + r0 * 132 + col)       = va;
            *(float2*)(sC + (r0 + 8) * 132 + col) = vb;
        }
    }
}

// ---------------------------------------------------------------- edge kernel
__global__ void __launch_bounds__(THREADS, 2)
edge_kernel(const float* __restrict__ x, const float* __restrict__ edge_attr,
            const int* __restrict__ edge_index,
            const float* __restrict__ b1, const float* __restrict__ g1, const float* __restrict__ t1,
            const float* __restrict__ b2, const float* __restrict__ g2, const float* __restrict__ t2,
            const float* __restrict__ b3, const float* __restrict__ g3, const float* __restrict__ t3,
            const float* __restrict__ b4,
            float* __restrict__ out_edge)
{
    extern __shared__ uint2 smem2[];
    uint2* sA = smem2;                   // [64 rows][SA2 kpairs]; aliased as f32 staging
    __shared__ float  sPar[10 * 128];
    __shared__ float2 sPart[MTILE][4];
    __shared__ int    sSrc[MTILE], sDst[MTILE];

    int tid = threadIdx.x;
    int w   = tid >> 5;
    int rb  = (w >> 2) * 32;
    int wn  = w & 3;
    int nb0 = wn * 32;
    size_t ebase = (size_t)blockIdx.x * MTILE;

    if (tid < 128) {
        sPar[0*128+tid] = b1[tid]; sPar[1*128+tid] = g1[tid]; sPar[2*128+tid] = t1[tid];
        sPar[3*128+tid] = b2[tid]; sPar[4*128+tid] = g2[tid]; sPar[5*128+tid] = t2[tid];
        sPar[6*128+tid] = b3[tid]; sPar[7*128+tid] = g3[tid]; sPar[8*128+tid] = t3[tid];
        sPar[9*128+tid] = b4[tid];
    } else if (tid < 128 + MTILE) {
        int r = tid - 128;
        sSrc[r] = edge_index[ebase + r];
        sDst[r] = edge_index[(size_t)NE + ebase + r];
    }
    __syncthreads();

    float acc[2][4][4];
    zero_acc(acc);

    // ---- layer 1: K = 384 in 3 chunks, accumulate in registers
    #pragma unroll 1
    for (int c = 0; c < 3; ++c) {
        #pragma unroll
        for (int i = tid; i < MTILE * 32; i += THREADS) {
            int r = i >> 5, j = i & 31;
            const float* src = (c == 0) ? edge_attr + (ebase + r) * H
                                        : x + (size_t)(c == 1 ? sSrc[r] : sDst[r]) * H;
            float4 v = ((const float4*)src)[j];
            uint2 p0 = splitp(make_float2(v.x, v.y));
            uint2 p1 = splitp(make_float2(v.z, v.w));
            *(uint4*)(sA + r * SA2 + 2 * j) = make_uint4(p0.x, p0.y, p1.x, p1.y);
        }
        __syncthreads();
        gemm64(sA, g_wB + (size_t)c * 8192, acc, rb, nb0);
        __syncthreads();
    }

    // ---- layers 2..4 (chunks 3,4,5)
    #pragma unroll 1
    for (int l = 0; l < 3; ++l) {
        epi_ln(acc, sPar, l, sA, sPart, rb, nb0, wn);
        __syncthreads();
        zero_acc(acc);
        gemm64(sA, g_wB + (size_t)(3 + l) * 8192, acc, rb, nb0);
        __syncthreads();
    }

    // ---- final: + b4 -> staging (aliases sA), residual write + atomic scatter
    epi_final(acc, sPar, (float*)sA, rb, nb0);
    __syncthreads();

    #pragma unroll
    for (int i = tid; i < MTILE * 32; i += THREADS) {
        int r = i >> 5, j = i & 31;
        float4 val = *(float4*)((float*)sA + r * 132 + j * 4);
        size_t e = ebase + r;
        float4 ea = ((const float4*)(edge_attr + e * H))[j];
        float4 o;
        o.x = ea.x + val.x; o.y = ea.y + val.y; o.z = ea.z + val.z; o.w = ea.w + val.w;
        ((float4*)(out_edge + e * H))[j] = o;
        atomicAdd((float4*)(g_agg + (size_t)sDst[r] * H + j * 4), val);
    }
}

// ---------------------------------------------------------------- node kernel
__global__ void __launch_bounds__(THREADS, 2)
node_kernel(const float* __restrict__ x,
            const float* __restrict__ b1, const float* __restrict__ g1, const float* __restrict__ t1,
            const float* __restrict__ b2, const float* __restrict__ g2, const float* __restrict__ t2,
            const float* __restrict__ b3, const float* __restrict__ g3, const float* __restrict__ t3,
            const float* __restrict__ b4,
            float* __restrict__ out_node)
{
    extern __shared__ uint2 smem2[];
    uint2* sA = smem2;
    __shared__ float  sPar[10 * 128];
    __shared__ float2 sPart[MTILE][4];

    int tid = threadIdx.x;
    int w   = tid >> 5;
    int rb  = (w >> 2) * 32;
    int wn  = w & 3;
    int nb0 = wn * 32;
    size_t nbase = (size_t)blockIdx.x * MTILE;

    if (tid < 128) {
        sPar[0*128+tid] = b1[tid]; sPar[1*128+tid] = g1[tid]; sPar[2*128+tid] = t1[tid];
        sPar[3*128+tid] = b2[tid]; sPar[4*128+tid] = g2[tid]; sPar[5*128+tid] = t2[tid];
        sPar[6*128+tid] = b3[tid]; sPar[7*128+tid] = g3[tid]; sPar[8*128+tid] = t3[tid];
        sPar[9*128+tid] = b4[tid];
    }
    __syncthreads();

    float acc[2][4][4];
    zero_acc(acc);

    // ---- layer 1: K = 256 in 2 chunks ([x | agg]); agg re-zeroed after read
    #pragma unroll 1
    for (int c = 0; c < 2; ++c) {
        #pragma unroll
        for (int i = tid; i < MTILE * 32; i += THREADS) {
            int r = i >> 5, j = i & 31;
            size_t node = nbase + r;
            float4 v = make_float4(0.f, 0.f, 0.f, 0.f);
            if (node < NN) {
                if (c == 0) {
                    v = ((const float4*)(x + node * H))[j];
                } else {
                    float4* ap = (float4*)(g_agg + node * H) + j;
                    v = *ap;
                    *ap = make_float4(0.f, 0.f, 0.f, 0.f);  // restore invariant
                }
            }
            uint2 p0 = splitp(make_float2(v.x, v.y));
            uint2 p1 = splitp(make_float2(v.z, v.w));
            *(uint4*)(sA + r * SA2 + 2 * j) = make_uint4(p0.x, p0.y, p1.x, p1.y);
        }
        __syncthreads();
        gemm64(sA, g_wB + (size_t)(6 + c) * 8192, acc, rb, nb0);
        __syncthreads();
    }

    // ---- layers 2..4 (chunks 8,9,10)
    #pragma unroll 1
    for (int l = 0; l < 3; ++l) {
        epi_ln(acc, sPar, l, sA, sPart, rb, nb0, wn);
        __syncthreads();
        zero_acc(acc);
        gemm64(sA, g_wB + (size_t)(8 + l) * 8192, acc, rb, nb0);
        __syncthreads();
    }

    epi_final(acc, sPar, (float*)sA, rb, nb0);
    __syncthreads();

    #pragma unroll
    for (int i = tid; i < MTILE * 32; i += THREADS) {
        int r = i >> 5, j = i & 31;
        size_t node = nbase + r;
        if (node < NN) {
            float4 val = *(float4*)((float*)sA + r * 132 + j * 4);
            float4 xv = ((const float4*)(x + node * H))[j];
            float4 o;
            o.x = xv.x + val.x; o.y = xv.y + val.y; o.z = xv.z + val.z; o.w = xv.w + val.w;
            ((float4*)(out_node + node * H))[j] = o;
        }
    }
}

// ---------------------------------------------------------------- launch
extern "C" void kernel_launch(void* const* d_in, const int* in_sizes, int n_in,
                              void* d_out, int out_size)
{
    const float* x          = (const float*)d_in[0];
    const float* edge_attr  = (const float*)d_in[1];
    const int*   edge_index = (const int*)d_in[2];

    const float* eW1 = (const float*)d_in[3];  const float* eb1 = (const float*)d_in[4];
    const float* eW2 = (const float*)d_in[5];  const float* eb2 = (const float*)d_in[6];
    const float* eW3 = (const float*)d_in[7];  const float* eb3 = (const float*)d_in[8];
    const float* eW4 = (const float*)d_in[9];  const float* eb4 = (const float*)d_in[10];
    const float* eg1 = (const float*)d_in[11]; const float* et1 = (const float*)d_in[12];
    const float* eg2 = (const float*)d_in[13]; const float* et2 = (const float*)d_in[14];
    const float* eg3 = (const float*)d_in[15]; const float* et3 = (const float*)d_in[16];

    const float* nW1 = (const float*)d_in[17]; const float* nb1 = (const float*)d_in[18];
    const float* nW2 = (const float*)d_in[19]; const float* nb2 = (const float*)d_in[20];
    const float* nW3 = (const float*)d_in[21]; const float* nb3 = (const float*)d_in[22];
    const float* nW4 = (const float*)d_in[23]; const float* nb4 = (const float*)d_in[24];
    const float* ng1 = (const float*)d_in[25]; const float* nt1 = (const float*)d_in[26];
    const float* ng2 = (const float*)d_in[27]; const float* nt2 = (const float*)d_in[28];
    const float* ng3 = (const float*)d_in[29]; const float* nt3 = (const float*)d_in[30];

    float* out_node = (float*)d_out;                   // [NN*H]
    float* out_edge = (float*)d_out + (size_t)NN * H;  // [NE*H]

    const int SMEM = MTILE * SA2 * 8;  // 34816 B
    cudaFuncSetAttribute(edge_kernel, cudaFuncAttributeMaxDynamicSharedMemorySize, SMEM);
    cudaFuncSetAttribute(node_kernel, cudaFuncAttributeMaxDynamicSharedMemorySize, SMEM);

    wprep_kernel<<<(11 * 8192 + 255) / 256, 256>>>(eW1, eW2, eW3, eW4,
                                                   nW1, nW2, nW3, nW4);

    edge_kernel<<<NE / MTILE, THREADS, SMEM>>>(
        x, edge_attr, edge_index,
        eb1, eg1, et1, eb2, eg2, et2, eb3, eg3, et3, eb4,
        out_edge);

    node_kernel<<<(NN + MTILE - 1) / MTILE, THREADS, SMEM>>>(
        x,
        nb1, ng1, nt1, nb2, ng2, nt2, nb3, ng3, nt3, nb4,
        out_node);
}

// round 13
// speedup vs baseline: 1.5362x; 1.3059x over previous
#include <cuda_runtime.h>
#include <cuda_bf16.h>
#include <cstdint>

#define H        128
#define NE       400000
#define NN       50000
#define THREADS  256
#define MTILE    64
#define SA2      68    // uint2 stride for A kpairs (mod 16 == 4 -> conflict-free)

// scratch (no cudaMalloc allowed)
__device__ float g_agg[NN * H];    // scatter accumulator (zero invariant)
__device__ float g_P1[NN * H];     // x @ eW1[128:256]  (src transform)
__device__ float g_P2[NN * H];     // x @ eW1[256:384]  (dst transform)
// prepacked split-bf16 weights: 11 chunks x [64 kpairs][128 cols] uint2(hi,lo)
__device__ uint2 g_wB[11 * 8192];

// ---------------------------------------------------------------- helpers
__device__ __forceinline__ void split2(float2 v, uint32_t& hi, uint32_t& lo) {
    __nv_bfloat162 h = __float22bfloat162_rn(v);
    float2 hf = __bfloat1622float2(h);
    __nv_bfloat162 l = __float22bfloat162_rn(make_float2(v.x - hf.x, v.y - hf.y));
    hi = *(uint32_t*)&h;
    lo = *(uint32_t*)&l;
}
__device__ __forceinline__ uint2 splitp(float2 v) {
    uint2 r; split2(v, r.x, r.y); return r;
}

__device__ __forceinline__ void mma_bf16(float d[4], const uint32_t a[4],
                                         uint32_t b0, uint32_t b1) {
    asm volatile(
        "mma.sync.aligned.m16n8k16.row.col.f32.bf16.bf16.f32 "
        "{%0,%1,%2,%3}, {%4,%5,%6,%7}, {%8,%9}, {%0,%1,%2,%3};"
        : "+f"(d[0]), "+f"(d[1]), "+f"(d[2]), "+f"(d[3])
        : "r"(a[0]), "r"(a[1]), "r"(a[2]), "r"(a[3]), "r"(b0), "r"(b1));
}

// ---------------------------------------------------------------- wprep
// chunks: 0-2 eW1(k0=0,128,256), 3 eW2, 4 eW3, 5 eW4, 6-7 nW1(k0=0,128), 8 nW2, 9 nW3, 10 nW4
__global__ void wprep_kernel(const float* __restrict__ eW1, const float* __restrict__ eW2,
                             const float* __restrict__ eW3, const float* __restrict__ eW4,
                             const float* __restrict__ nW1, const float* __restrict__ nW2,
                             const float* __restrict__ nW3, const float* __restrict__ nW4)
{
    int i = blockIdx.x * blockDim.x + threadIdx.x;
    if (i >= 11 * 8192) return;
    int chunk = i >> 13, e = i & 8191;
    int kp = e >> 7, col = e & 127;
    const float* W; int k0;
    switch (chunk) {
        case 0:  W = eW1; k0 = 0;   break;
        case 1:  W = eW1; k0 = 128; break;
        case 2:  W = eW1; k0 = 256; break;
        case 3:  W = eW2; k0 = 0;   break;
        case 4:  W = eW3; k0 = 0;   break;
        case 5:  W = eW4; k0 = 0;   break;
        case 6:  W = nW1; k0 = 0;   break;
        case 7:  W = nW1; k0 = 128; break;
        case 8:  W = nW2; k0 = 0;   break;
        case 9:  W = nW3; k0 = 0;   break;
        default: W = nW4; k0 = 0;   break;
    }
    float2 v = make_float2(W[(size_t)(k0 + 2 * kp)     * H + col],
                           W[(size_t)(k0 + 2 * kp + 1) * H + col]);
    g_wB[i] = splitp(v);
}

// ---------------------------------------------------------------- gemm
// Warp tile m32 x n32, software-pipelined ksteps, grouped split terms.
struct Frag {
    uint32_t ah[2][4], al[2][4];
    uint2    b0[4],    b1[4];
};

__device__ __forceinline__ void load_frag(Frag& f, const uint2* A0,
                                          const uint2* __restrict__ gB,
                                          int kp, int nb0, int gid) {
    #pragma unroll
    for (int mb = 0; mb < 2; ++mb) {
        const uint2* Ar0 = A0 + mb * 16 * SA2 + kp;
        const uint2* Ar8 = Ar0 + 8 * SA2;
        uint2 q0 = Ar0[0], q1 = Ar8[0], q2 = Ar0[4], q3 = Ar8[4];
        f.ah[mb][0] = q0.x; f.al[mb][0] = q0.y;
        f.ah[mb][1] = q1.x; f.al[mb][1] = q1.y;
        f.ah[mb][2] = q2.x; f.al[mb][2] = q2.y;
        f.ah[mb][3] = q3.x; f.al[mb][3] = q3.y;
    }
    const uint2* Bp0 = gB + kp * 128 + nb0 + gid;
    const uint2* Bp1 = Bp0 + 4 * 128;
    #pragma unroll
    for (int nt = 0; nt < 4; ++nt) {
        f.b0[nt] = __ldg(Bp0 + nt * 8);
        f.b1[nt] = __ldg(Bp1 + nt * 8);
    }
}

__device__ __forceinline__ void mma_frag(const Frag& f, float acc[2][4][4]) {
    #pragma unroll
    for (int nt = 0; nt < 4; ++nt)
        #pragma unroll
        for (int mb = 0; mb < 2; ++mb)
            mma_bf16(acc[mb][nt], f.ah[mb], f.b0[nt].x, f.b1[nt].x);
    #pragma unroll
    for (int nt = 0; nt < 4; ++nt)
        #pragma unroll
        for (int mb = 0; mb < 2; ++mb)
            mma_bf16(acc[mb][nt], f.al[mb], f.b0[nt].x, f.b1[nt].x);
    #pragma unroll
    for (int nt = 0; nt < 4; ++nt)
        #pragma unroll
        for (int mb = 0; mb < 2; ++mb)
            mma_bf16(acc[mb][nt], f.ah[mb], f.b0[nt].y, f.b1[nt].y);
}

__device__ __forceinline__ void gemm64(const uint2* sA, const uint2* __restrict__ gB,
                                       float acc[2][4][4], int rb, int nb0) {
    int lane = threadIdx.x & 31;
    int gid  = lane >> 2, tig = lane & 3;
    const uint2* A0 = sA + (rb + gid) * SA2;
    Frag fa, fb;
    load_frag(fa, A0, gB, tig, nb0, gid);
    #pragma unroll
    for (int ks = 0; ks < 8; ++ks) {
        if (ks & 1) {
            if (ks < 7) load_frag(fa, A0, gB, (ks + 1) * 8 + tig, nb0, gid);
            mma_frag(fb, acc);
        } else {
            if (ks < 7) load_frag(fb, A0, gB, (ks + 1) * 8 + tig, nb0, gid);
            mma_frag(fa, acc);
        }
    }
}

__device__ __forceinline__ void zero_acc(float acc[2][4][4]) {
    #pragma unroll
    for (int mb = 0; mb < 2; ++mb)
        #pragma unroll
        for (int nt = 0; nt < 4; ++nt)
            #pragma unroll
            for (int c = 0; c < 4; ++c) acc[mb][nt][c] = 0.0f;
}

// gathered add: acc += P[idx[row]][col] (precomputed node transforms)
__device__ __forceinline__ void add_gathered(float acc[2][4][4],
                                             const float* __restrict__ P,
                                             const int* sIdx, int rb, int nb0) {
    int lane = threadIdx.x & 31;
    int gid  = lane >> 2, tig = lane & 3;
    #pragma unroll
    for (int mb = 0; mb < 2; ++mb) {
        int r0 = rb + mb * 16 + gid;
        const float* p0 = P + (size_t)sIdx[r0] * H;
        const float* p1 = P + (size_t)sIdx[r0 + 8] * H;
        #pragma unroll
        for (int nt = 0; nt < 4; ++nt) {
            int col = nb0 + nt * 8 + 2 * tig;
            float2 v0 = *(const float2*)(p0 + col);
            float2 v1 = *(const float2*)(p1 + col);
            acc[mb][nt][0] += v0.x; acc[mb][nt][1] += v0.y;
            acc[mb][nt][2] += v1.x; acc[mb][nt][3] += v1.y;
        }
    }
}

// bias + ReLU + LayerNorm (rows split across 4 n-warps); split-store into sA
__device__ __forceinline__ void epi_ln(float acc[2][4][4], const float* sPar, int l,
                                       uint2* sA, float2 (*sPart)[4], int rb, int nb0,
                                       int wn) {
    int lane = threadIdx.x & 31;
    int gid  = lane >> 2, tig = lane & 3;
    const float* bb = sPar + l * 3 * 128;
    const float* gg = bb + 128;
    const float* tt = bb + 256;
    float s[4] = {0.f, 0.f, 0.f, 0.f}, s2[4] = {0.f, 0.f, 0.f, 0.f};
    #pragma unroll
    for (int mb = 0; mb < 2; ++mb)
        #pragma unroll
        for (int nt = 0; nt < 4; ++nt) {
            int col = nb0 + nt * 8 + 2 * tig;
            float2 b = *(const float2*)(bb + col);
            float t0 = fmaxf(acc[mb][nt][0] + b.x, 0.f);
            float t1 = fmaxf(acc[mb][nt][1] + b.y, 0.f);
            float t2 = fmaxf(acc[mb][nt][2] + b.x, 0.f);
            float t3 = fmaxf(acc[mb][nt][3] + b.y, 0.f);
            acc[mb][nt][0] = t0; acc[mb][nt][1] = t1;
            acc[mb][nt][2] = t2; acc[mb][nt][3] = t3;
            s[2*mb]   += t0 + t1; s2[2*mb]   = fmaf(t0, t0, fmaf(t1, t1, s2[2*mb]));
            s[2*mb+1] += t2 + t3; s2[2*mb+1] = fmaf(t2, t2, fmaf(t3, t3, s2[2*mb+1]));
        }
    #pragma unroll
    for (int m = 1; m <= 2; m <<= 1)
        #pragma unroll
        for (int k = 0; k < 4; ++k) {
            s[k]  += __shfl_xor_sync(0xffffffffu, s[k],  m);
            s2[k] += __shfl_xor_sync(0xffffffffu, s2[k], m);
        }
    int R[4] = {rb + gid, rb + gid + 8, rb + 16 + gid, rb + 24 + gid};
    if (tig == 0) {
        #pragma unroll
        for (int k = 0; k < 4; ++k) sPart[R[k]][wn] = make_float2(s[k], s2[k]);
    }
    __syncthreads();
    float mean[4], inv[4];
    #pragma unroll
    for (int k = 0; k < 4; ++k) {
        float2 p0 = sPart[R[k]][0], p1 = sPart[R[k]][1];
        float2 p2 = sPart[R[k]][2], p3 = sPart[R[k]][3];
        float sm = (p0.x + p1.x) + (p2.x + p3.x);
        float sq = (p0.y + p1.y) + (p2.y + p3.y);
        mean[k] = sm * 0.0078125f;
        inv[k]  = rsqrtf(fmaf(-mean[k], mean[k], sq * 0.0078125f) + 1e-5f);
    }
    #pragma unroll
    for (int mb = 0; mb < 2; ++mb)
        #pragma unroll
        for (int nt = 0; nt < 4; ++nt) {
            int col = nb0 + nt * 8 + 2 * tig;
            int kpo = col >> 1;
            float2 g = *(const float2*)(gg + col);
            float2 t = *(const float2*)(tt + col);
            float2 va, vb;
            va.x = fmaf((acc[mb][nt][0] - mean[2*mb]) * inv[2*mb], g.x, t.x);
            va.y = fmaf((acc[mb][nt][1] - mean[2*mb]) * inv[2*mb], g.y, t.y);
            vb.x = fmaf((acc[mb][nt][2] - mean[2*mb+1]) * inv[2*mb+1], g.x, t.x);
            vb.y = fmaf((acc[mb][nt][3] - mean[2*mb+1]) * inv[2*mb+1], g.y, t.y);
            sA[R[2*mb]   * SA2 + kpo] = splitp(va);
            sA[R[2*mb+1] * SA2 + kpo] = splitp(vb);
        }
}

// final layer: acc + b4 -> f32 staging (stride 132 floats; ALIASES sA)
__device__ __forceinline__ void epi_final(float acc[2][4][4], const float* sPar,
                                          float* sC, int rb, int nb0) {
    int lane = threadIdx.x & 31;
    int gid  = lane >> 2, tig = lane & 3;
    const float* b4 = sPar + 9 * 128;
    #pragma unroll
    for (int mb = 0; mb < 2; ++mb) {
        int r0 = rb + mb * 16 + gid;
        #pragma unroll
        for (int nt = 0; nt < 4; ++nt) {
            int col = nb0 + nt * 8 + 2 * tig;
            float2 b = *(const float2*)(b4 + col);
            float2 va, vb;
            va.x = acc[mb][nt][0] + b.x; va.y = acc[mb][nt][1] + b.y;
            vb.x = acc[mb][nt][2] + b.x; vb.y = acc[mb][nt][3] + b.y;
            *(float2*)(sC + r0 * 132 + col)       = va;
            *(float2*)(sC + (r0 + 8) * 132 + col) = vb;
        }
    }
}

// ---------------------------------------------------------------- prep kernel
// P1 = x @ eW1[128:256], P2 = x @ eW1[256:384]  (no bias, pure transforms)
__global__ void __launch_bounds__(THREADS, 2)
prep_kernel(const float* __restrict__ x)
{
    extern __shared__ uint2 smem2[];
    uint2* sA = smem2;
    int tid = threadIdx.x;
    int w   = tid >> 5;
    int rb  = (w >> 2) * 32;
    int wn  = w & 3;
    int nb0 = wn * 32;
    int lane = tid & 31;
    int gid  = lane >> 2, tig = lane & 3;
    size_t nbase = (size_t)blockIdx.x * MTILE;

    #pragma unroll
    for (int i = tid; i < MTILE * 32; i += THREADS) {
        int r = i >> 5, j = i & 31;
        size_t node = nbase + r;
        float4 v = make_float4(0.f, 0.f, 0.f, 0.f);
        if (node < NN) v = ((const float4*)(x + node * H))[j];
        uint2 p0 = splitp(make_float2(v.x, v.y));
        uint2 p1 = splitp(make_float2(v.z, v.w));
        *(uint4*)(sA + r * SA2 + 2 * j) = make_uint4(p0.x, p0.y, p1.x, p1.y);
    }
    __syncthreads();

    float acc[2][4][4];
    #pragma unroll 1
    for (int c = 0; c < 2; ++c) {
        zero_acc(acc);
        gemm64(sA, g_wB + (size_t)(1 + c) * 8192, acc, rb, nb0);
        float* P = (c == 0) ? g_P1 : g_P2;
        #pragma unroll
        for (int mb = 0; mb < 2; ++mb) {
            size_t r0 = nbase + rb + mb * 16 + gid;
            #pragma unroll
            for (int nt = 0; nt < 4; ++nt) {
                int col = nb0 + nt * 8 + 2 * tig;
                if (r0 < NN)
                    *(float2*)(P + r0 * H + col) = make_float2(acc[mb][nt][0], acc[mb][nt][1]);
                if (r0 + 8 < NN)
                    *(float2*)(P + (r0 + 8) * H + col) = make_float2(acc[mb][nt][2], acc[mb][nt][3]);
            }
        }
    }
}

// ---------------------------------------------------------------- edge kernel
__global__ void __launch_bounds__(THREADS, 2)
edge_kernel(const float* __restrict__ x, const float* __restrict__ edge_attr,
            const int* __restrict__ edge_index,
            const float* __restrict__ b1, const float* __restrict__ g1, const float* __restrict__ t1,
            const float* __restrict__ b2, const float* __restrict__ g2, const float* __restrict__ t2,
            const float* __restrict__ b3, const float* __restrict__ g3, const float* __restrict__ t3,
            const float* __restrict__ b4,
            float* __restrict__ out_edge)
{
    extern __shared__ uint2 smem2[];
    uint2* sA = smem2;                   // [64 rows][SA2 kpairs]; aliased as f32 staging
    __shared__ float  sPar[10 * 128];
    __shared__ float2 sPart[MTILE][4];
    __shared__ int    sSrc[MTILE], sDst[MTILE];

    int tid = threadIdx.x;
    int w   = tid >> 5;
    int rb  = (w >> 2) * 32;
    int wn  = w & 3;
    int nb0 = wn * 32;
    size_t ebase = (size_t)blockIdx.x * MTILE;

    if (tid < 128) {
        sPar[0*128+tid] = b1[tid]; sPar[1*128+tid] = g1[tid]; sPar[2*128+tid] = t1[tid];
        sPar[3*128+tid] = b2[tid]; sPar[4*128+tid] = g2[tid]; sPar[5*128+tid] = t2[tid];
        sPar[6*128+tid] = b3[tid]; sPar[7*128+tid] = g3[tid]; sPar[8*128+tid] = t3[tid];
        sPar[9*128+tid] = b4[tid];
    } else if (tid < 128 + MTILE) {
        int r = tid - 128;
        sSrc[r] = edge_index[ebase + r];
        sDst[r] = edge_index[(size_t)NE + ebase + r];
    }
    __syncthreads();

    float acc[2][4][4];
    zero_acc(acc);

    // ---- layer 1: edge_attr gemm (chunk 0) + gathered precomputed node parts
    #pragma unroll
    for (int i = tid; i < MTILE * 32; i += THREADS) {
        int r = i >> 5, j = i & 31;
        float4 v = ((const float4*)(edge_attr + (ebase + r) * H))[j];
        uint2 p0 = splitp(make_float2(v.x, v.y));
        uint2 p1 = splitp(make_float2(v.z, v.w));
        *(uint4*)(sA + r * SA2 + 2 * j) = make_uint4(p0.x, p0.y, p1.x, p1.y);
    }
    __syncthreads();
    gemm64(sA, g_wB, acc, rb, nb0);
    add_gathered(acc, g_P1, sSrc, rb, nb0);
    add_gathered(acc, g_P2, sDst, rb, nb0);
    __syncthreads();

    // ---- layers 2..4 (chunks 3,4,5)
    #pragma unroll 1
    for (int l = 0; l < 3; ++l) {
        epi_ln(acc, sPar, l, sA, sPart, rb, nb0, wn);
        __syncthreads();
        zero_acc(acc);
        gemm64(sA, g_wB + (size_t)(3 + l) * 8192, acc, rb, nb0);
        __syncthreads();
    }

    // ---- final: + b4 -> staging (aliases sA), residual write + atomic scatter
    epi_final(acc, sPar, (float*)sA, rb, nb0);
    __syncthreads();

    #pragma unroll
    for (int i = tid; i < MTILE * 32; i += THREADS) {
        int r = i >> 5, j = i & 31;
        float4 val = *(float4*)((float*)sA + r * 132 + j * 4);
        size_t e = ebase + r;
        float4 ea = ((const float4*)(edge_attr + e * H))[j];
        float4 o;
        o.x = ea.x + val.x; o.y = ea.y + val.y; o.z = ea.z + val.z; o.w = ea.w + val.w;
        ((float4*)(out_edge + e * H))[j] = o;
        atomicAdd((float4*)(g_agg + (size_t)sDst[r] * H + j * 4), val);
    }
}

// ---------------------------------------------------------------- node kernel
__global__ void __launch_bounds__(THREADS, 2)
node_kernel(const float* __restrict__ x,
            const float* __restrict__ b1, const float* __restrict__ g1, const float* __restrict__ t1,
            const float* __restrict__ b2, const float* __restrict__ g2, const float* __restrict__ t2,
            const float* __restrict__ b3, const float* __restrict__ g3, const float* __restrict__ t3,
            const float* __restrict__ b4,
            float* __restrict__ out_node)
{
    extern __shared__ uint2 smem2[];
    uint2* sA = smem2;
    __shared__ float  sPar[10 * 128];
    __shared__ float2 sPart[MTILE][4];

    int tid = threadIdx.x;
    int w   = tid >> 5;
    int rb  = (w >> 2) * 32;
    int wn  = w & 3;
    int nb0 = wn * 32;
    size_t nbase = (size_t)blockIdx.x * MTILE;

    if (tid < 128) {
        sPar[0*128+tid] = b1[tid]; sPar[1*128+tid] = g1[tid]; sPar[2*128+tid] = t1[tid];
        sPar[3*128+tid] = b2[tid]; sPar[4*128+tid] = g2[tid]; sPar[5*128+tid] = t2[tid];
        sPar[6*128+tid] = b3[tid]; sPar[7*128+tid] = g3[tid]; sPar[8*128+tid] = t3[tid];
        sPar[9*128+tid] = b4[tid];
    }
    __syncthreads();

    float acc[2][4][4];
    zero_acc(acc);

    // ---- layer 1: K = 256 in 2 chunks ([x | agg]); agg re-zeroed after read
    #pragma unroll 1
    for (int c = 0; c < 2; ++c) {
        #pragma unroll
        for (int i = tid; i < MTILE * 32; i += THREADS) {
            int r = i >> 5, j = i & 31;
            size_t node = nbase + r;
            float4 v = make_float4(0.f, 0.f, 0.f, 0.f);
            if (node < NN) {
                if (c == 0) {
                    v = ((const float4*)(x + node * H))[j];
                } else {
                    float4* ap = (float4*)(g_agg + node * H) + j;
                    v = *ap;
                    *ap = make_float4(0.f, 0.f, 0.f, 0.f);  // restore invariant
                }
            }
            uint2 p0 = splitp(make_float2(v.x, v.y));
            uint2 p1 = splitp(make_float2(v.z, v.w));
            *(uint4*)(sA + r * SA2 + 2 * j) = make_uint4(p0.x, p0.y, p1.x, p1.y);
        }
        __syncthreads();
        gemm64(sA, g_wB + (size_t)(6 + c) * 8192, acc, rb, nb0);
        __syncthreads();
    }

    // ---- layers 2..4 (chunks 8,9,10)
    #pragma unroll 1
    for (int l = 0; l < 3; ++l) {
        epi_ln(acc, sPar, l, sA, sPart, rb, nb0, wn);
        __syncthreads();
        zero_acc(acc);
        gemm64(sA, g_wB + (size_t)(8 + l) * 8192, acc, rb, nb0);
        __syncthreads();
    }

    epi_final(acc, sPar, (float*)sA, rb, nb0);
    __syncthreads();

    #pragma unroll
    for (int i = tid; i < MTILE * 32; i += THREADS) {
        int r = i >> 5, j = i & 31;
        size_t node = nbase + r;
        if (node < NN) {
            float4 val = *(float4*)((float*)sA + r * 132 + j * 4);
            float4 xv = ((const float4*)(x + node * H))[j];
            float4 o;
            o.x = xv.x + val.x; o.y = xv.y + val.y; o.z = xv.z + val.z; o.w = xv.w + val.w;
            ((float4*)(out_node + node * H))[j] = o;
        }
    }
}

// ---------------------------------------------------------------- launch
extern "C" void kernel_launch(void* const* d_in, const int* in_sizes, int n_in,
                              void* d_out, int out_size)
{
    const float* x          = (const float*)d_in[0];
    const float* edge_attr  = (const float*)d_in[1];
    const int*   edge_index = (const int*)d_in[2];

    const float* eW1 = (const float*)d_in[3];  const float* eb1 = (const float*)d_in[4];
    const float* eW2 = (const float*)d_in[5];  const float* eb2 = (const float*)d_in[6];
    const float* eW3 = (const float*)d_in[7];  const float* eb3 = (const float*)d_in[8];
    const float* eW4 = (const float*)d_in[9];  const float* eb4 = (const float*)d_in[10];
    const float* eg1 = (const float*)d_in[11]; const float* et1 = (const float*)d_in[12];
    const float* eg2 = (const float*)d_in[13]; const float* et2 = (const float*)d_in[14];
    const float* eg3 = (const float*)d_in[15]; const float* et3 = (const float*)d_in[16];

    const float* nW1 = (const float*)d_in[17]; const float* nb1 = (const float*)d_in[18];
    const float* nW2 = (const float*)d_in[19]; const float* nb2 = (const float*)d_in[20];
    const float* nW3 = (const float*)d_in[21]; const float* nb3 = (const float*)d_in[22];
    const float* nW4 = (const float*)d_in[23]; const float* nb4 = (const float*)d_in[24];
    const float* ng1 = (const float*)d_in[25]; const float* nt1 = (const float*)d_in[26];
    const float* ng2 = (const float*)d_in[27]; const float* nt2 = (const float*)d_in[28];
    const float* ng3 = (const float*)d_in[29]; const float* nt3 = (const float*)d_in[30];

    float* out_node = (float*)d_out;                   // [NN*H]
    float* out_edge = (float*)d_out + (size_t)NN * H;  // [NE*H]

    const int SMEM = MTILE * SA2 * 8;  // 34816 B
    cudaFuncSetAttribute(prep_kernel, cudaFuncAttributeMaxDynamicSharedMemorySize, SMEM);
    cudaFuncSetAttribute(edge_kernel, cudaFuncAttributeMaxDynamicSharedMemorySize, SMEM);
    cudaFuncSetAttribute(node_kernel, cudaFuncAttributeMaxDynamicSharedMemorySize, SMEM);

    wprep_kernel<<<(11 * 8192 + 255) / 256, 256>>>(eW1, eW2, eW3, eW4,
                                                   nW1, nW2, nW3, nW4);

    prep_kernel<<<(NN + MTILE - 1) / MTILE, THREADS, SMEM>>>(x);

    edge_kernel<<<NE / MTILE, THREADS, SMEM>>>(
        x, edge_attr, edge_index,
        eb1, eg1, et1, eb2, eg2, et2, eb3, eg3, et3, eb4,
        out_edge);

    node_kernel<<<(NN + MTILE - 1) / MTILE, THREADS, SMEM>>>(
        x,
        nb1, ng1, nt1, nb2, ng2, nt2, nb3, ng3, nt3, nb4,
        out_node);
}